// round 10
// baseline (speedup 1.0000x reference)
#include <cuda_runtime.h>
#include <cuda_bf16.h>
#include <cstdint>

#define N_ 128
#define C_ 81
#define A_ 8732
#define A4_ 2183          // A_/4 exactly
#define NB 4096
#define DYN_BYTES (NB * 4)   // one 4096-bin histogram (consumers only)

// Scratch (device globals — no allocations allowed)
__device__ unsigned g_con[N_ * A_];        // focal bits (dl==0 rows), positives = 0u
__device__ float    g_partcon[N_ * 16];
__device__ int      g_partpos[N_ * 16];
__device__ float    g_row[N_];
__device__ unsigned g_done[N_];            // per-row producer count (self-resetting)
__device__ unsigned g_count;               // consumer arrivals (self-resetting)

// ---------------------------------------------------------------------------
// grid = 1152 producers (bid = 9n+j) then 128 consumers (bid = 1152+n).
// block = 256. Producers: focal loss slice. Consumers: loc/sl1, wait on row,
// two-level histogram top-k, row loss; last consumer -> mean.
// ---------------------------------------------------------------------------
__global__ __launch_bounds__(256, 8) void k_all(const float* __restrict__ ploc,
                                                const float* __restrict__ plabel,
                                                const float* __restrict__ gloc,
                                                const int*   __restrict__ glabel,
                                                const int*   __restrict__ domain_label,
                                                const float* __restrict__ dboxes,
                                                float* __restrict__ out)
{
    extern __shared__ unsigned s_hist[];   // 4096 bins (consumers only)
    __shared__ float    s_redf[8];
    __shared__ int      s_redi[8];
    __shared__ unsigned s_wc[8];
    __shared__ int      s_B, s_B2;
    __shared__ unsigned s_kk, s_kk2;
    __shared__ unsigned s_last;

    const int bid = blockIdx.x;
    const int tid = threadIdx.x;
    const int wid = tid >> 5, lane = tid & 31;

    if (bid < 9 * N_) {
        // ===================== producer =====================
        const int n = bid / 9;
        const int j = bid - n * 9;
        if (domain_label[n] != 0) return;

        int idx = j * 256 + tid;
        bool valid = (idx < A4_);
        int ii = valid ? idx : (A4_ - 1);

        const float4* P = (const float4*)(plabel + (size_t)n * C_ * A_) + ii;
        int4 g = ((const int4*)(glabel + (size_t)n * A_))[ii];

        float4 s  = make_float4(0.f, 0.f, 0.f, 0.f);
        float4 xg = make_float4(0.f, 0.f, 0.f, 0.f);
#pragma unroll 3
        for (int c = 0; c < C_; c++) {
            float4 x = __ldcs(P);
            P += A4_;
            if (c == g.x) xg.x = x.x;
            if (c == g.y) xg.y = x.y;
            if (c == g.z) xg.z = x.z;
            if (c == g.w) xg.w = x.w;
            s.x += __expf(x.x); s.y += __expf(x.y);
            s.z += __expf(x.z); s.w += __expf(x.w);
        }

        float lp0 = xg.x - __logf(s.x), lp1 = xg.y - __logf(s.y);
        float lp2 = xg.z - __logf(s.z), lp3 = xg.w - __logf(s.w);
        float o0 = 1.f - __expf(lp0), o1 = 1.f - __expf(lp1);
        float o2 = 1.f - __expf(lp2), o3 = 1.f - __expf(lp3);
        float c0 = -0.25f * o0 * o0 * lp0;
        float c1 = -0.25f * o1 * o1 * lp1;
        float c2 = -0.25f * o2 * o2 * lp2;
        float c3 = -0.25f * o3 * o3 * lp3;

        bool m0 = g.x > 0, m1 = g.y > 0, m2 = g.z > 0, m3 = g.w > 0;

        uint4 cw;
        cw.x = m0 ? 0u : __float_as_uint(c0);
        cw.y = m1 ? 0u : __float_as_uint(c1);
        cw.z = m2 ? 0u : __float_as_uint(c2);
        cw.w = m3 ? 0u : __float_as_uint(c3);
        ((uint4*)g_con)[(size_t)n * A4_ + ii] = cw;

        float contrib = 0.f;
        int pc = 0;
        if (valid) {
            if (m0) { contrib += c0; pc++; }
            if (m1) { contrib += c1; pc++; }
            if (m2) { contrib += c2; pc++; }
            if (m3) { contrib += c3; pc++; }
        }
        for (int o = 16; o > 0; o >>= 1) {
            contrib += __shfl_down_sync(0xffffffffu, contrib, o);
            pc      += __shfl_down_sync(0xffffffffu, pc, o);
        }
        if (lane == 0) { s_redf[wid] = contrib; s_redi[wid] = pc; }
        __syncthreads();   // all block writes (incl. g_con) happen-before tid0 below
        if (tid == 0) {
            float t = 0.f; int tp = 0;
#pragma unroll
            for (int q = 0; q < 8; q++) { t += s_redf[q]; tp += s_redi[q]; }
            g_partcon[n * 16 + j] = t;
            g_partpos[n * 16 + j] = tp;
            __threadfence();                  // release
            atomicAdd(&g_done[n], 1u);
        }
        return;
    }

    // ===================== consumer =====================
    const int n  = bid - 9 * N_;
    const int dl = domain_label[n];
    float rowval = 0.f;

    if (dl == 0) {
        for (int i = tid; i < NB; i += 256) s_hist[i] = 0u;

        // ---- loc / smooth-L1 (independent of producers) ----
        const int4*   G  = (const int4*)(glabel + (size_t)n * A_);
        const float4* PL = (const float4*)(ploc + (size_t)n * 4 * A_);
        const float4* GL = (const float4*)(gloc + (size_t)n * 4 * A_);
        const float4* DB = (const float4*)dboxes;
        float acc = 0.f;     // sl1 + above1 + above2
        for (int grp = tid; grp < A4_; grp += 256) {
            int4 g = G[grp];
            bool m0 = g.x > 0, m1 = g.y > 0, m2 = g.z > 0, m3 = g.w > 0;
            if (m0 | m1 | m2 | m3) {
                float4 plx = PL[0 * A4_ + grp], ply = PL[1 * A4_ + grp];
                float4 plw = PL[2 * A4_ + grp], plh = PL[3 * A4_ + grp];
                float4 glx = GL[0 * A4_ + grp], gly = GL[1 * A4_ + grp];
                float4 glw = GL[2 * A4_ + grp], glh = GL[3 * A4_ + grp];
                float4 dbx = DB[0 * A4_ + grp], dby = DB[1 * A4_ + grp];
                float4 dbw = DB[2 * A4_ + grp], dbh = DB[3 * A4_ + grp];
#define SL1_LANE(M, PX, PY, PW, PH, GX, GY, GW, GH, DX, DY, DW, DH)           \
                if (M) {                                                      \
                    float v0 = 10.f * (GX - DX) / DW;                         \
                    float v1 = 10.f * (GY - DY) / DH;                         \
                    float v2 = 5.f * __logf(GW / DW);                         \
                    float v3 = 5.f * __logf(GH / DH);                         \
                    float d0 = PX - v0, d1 = PY - v1;                         \
                    float d2 = PW - v2, d3 = PH - v3;                         \
                    float ad;                                                 \
                    ad = fabsf(d0); acc += (ad < 1.f) ? 0.5f*d0*d0 : ad-0.5f; \
                    ad = fabsf(d1); acc += (ad < 1.f) ? 0.5f*d1*d1 : ad-0.5f; \
                    ad = fabsf(d2); acc += (ad < 1.f) ? 0.5f*d2*d2 : ad-0.5f; \
                    ad = fabsf(d3); acc += (ad < 1.f) ? 0.5f*d3*d3 : ad-0.5f; \
                }
                SL1_LANE(m0, plx.x, ply.x, plw.x, plh.x, glx.x, gly.x, glw.x, glh.x, dbx.x, dby.x, dbw.x, dbh.x)
                SL1_LANE(m1, plx.y, ply.y, plw.y, plh.y, glx.y, gly.y, glw.y, glh.y, dbx.y, dby.y, dbw.y, dbh.y)
                SL1_LANE(m2, plx.z, ply.z, plw.z, plh.z, glx.z, gly.z, glw.z, glh.z, dbx.z, dby.z, dbw.z, dbh.z)
                SL1_LANE(m3, plx.w, ply.w, plw.w, plh.w, glx.w, gly.w, glw.w, glh.w, dbx.w, dby.w, dbw.w, dbh.w)
#undef SL1_LANE
            }
        }

        // ---- wait for this row's 9 producers ----
        if (tid == 0) {
            while (atomicAdd(&g_done[n], 0u) < 9u) __nanosleep(32);
            g_done[n] = 0u;                   // reset for next replay
            __threadfence();                  // acquire
            float ps = 0.f; int pp = 0;
#pragma unroll
            for (int q = 0; q < 9; q++) { ps += g_partcon[n * 16 + q]; pp += g_partpos[n * 16 + q]; }
            s_redf[0] = ps; s_redi[0] = pp;
        }
        __syncthreads();
        const int   pos = s_redi[0];
        const float ps  = s_redf[0];

        if (pos > 0) {
            const unsigned k = (unsigned)((3 * pos > A_) ? A_ : 3 * pos);
            const uint4* gc = (const uint4*)g_con + (size_t)n * A4_;

            // ---- scan 1: hist on bits [31:20] ----
            for (int grp = tid; grp < A4_; grp += 256) {
                uint4 x = __ldcg(gc + grp);
                atomicAdd(&s_hist[x.x >> 20], 1u);
                atomicAdd(&s_hist[x.y >> 20], 1u);
                atomicAdd(&s_hist[x.z >> 20], 1u);
                atomicAdd(&s_hist[x.w >> 20], 1u);
            }
            __syncthreads();

            // ---- suffix scan (16 bins/thread) -> B, kk ----
#define FIND_BOUNDARY(KVAL, OUTB, OUTK)                                       \
            {                                                                 \
                unsigned lh[16], ls[16];                                      \
                int base = tid * 16;                                          \
                unsigned run = 0;                                             \
                _Pragma("unroll")                                             \
                for (int q = 15; q >= 0; q--) {                               \
                    lh[q] = s_hist[base + q];                                 \
                    run += lh[q];                                             \
                    ls[q] = run;                                              \
                }                                                             \
                unsigned incl = run;                                          \
                _Pragma("unroll")                                             \
                for (int o = 1; o < 32; o <<= 1) {                            \
                    unsigned v = __shfl_down_sync(0xffffffffu, incl, o);      \
                    if (lane + o < 32) incl += v;                             \
                }                                                             \
                if (lane == 0) s_wc[wid] = incl;                              \
                __syncthreads();                                              \
                unsigned hi = 0;                                              \
                _Pragma("unroll")                                             \
                for (int q = 0; q < 8; q++) if (q > wid) hi += s_wc[q];       \
                unsigned exh = hi + incl - run;   /* strictly above my bins */\
                _Pragma("unroll")                                             \
                for (int q = 0; q < 16; q++) {                                \
                    unsigned suf = exh + ls[q];                               \
                    unsigned gtc = suf - lh[q];                               \
                    if ((KVAL) <= suf && (KVAL) > gtc) {                      \
                        OUTB = base + q; OUTK = (KVAL) - gtc;                 \
                    }                                                         \
                }                                                             \
                __syncthreads();                                              \
            }
            FIND_BOUNDARY(k, s_B, s_kk)
            const unsigned B  = (unsigned)s_B;
            const unsigned kk = s_kk;

            for (int i = tid; i < NB; i += 256) s_hist[i] = 0u;
            __syncthreads();

            // ---- scan 2: sum above B, hist2 on bits [19:8] of bucket B ----
            for (int grp = tid; grp < A4_; grp += 256) {
                uint4 x = __ldcg(gc + grp);
#define P2(V)                                                                 \
                {                                                             \
                    unsigned b = (V) >> 20;                                   \
                    if (b > B) acc += __uint_as_float(V);                     \
                    else if (b == B) atomicAdd(&s_hist[((V) >> 8) & 0xFFFu], 1u); \
                }
                P2(x.x) P2(x.y) P2(x.z) P2(x.w)
#undef P2
            }
            __syncthreads();

            FIND_BOUNDARY(kk, s_B2, s_kk2)
            const unsigned B2  = (unsigned)s_B2;
            const unsigned kk2 = s_kk2;

            // ---- scan 3: sum bucket-B elems with mid-bits > B2 ----
            for (int grp = tid; grp < A4_; grp += 256) {
                uint4 x = __ldcg(gc + grp);
#define P3(V)                                                                 \
                if (((V) >> 20) == B && (((V) >> 8) & 0xFFFu) > B2)           \
                    acc += __uint_as_float(V);
                P3(x.x) P3(x.y) P3(x.z) P3(x.w)
#undef P3
            }

            for (int o = 16; o > 0; o >>= 1) acc += __shfl_down_sync(0xffffffffu, acc, o);
            if (lane == 0) s_redf[wid] = acc;
            __syncthreads();
            if (tid == 0) {
                float t = 0.f;
#pragma unroll
                for (int q = 0; q < 8; q++) t += s_redf[q];
                float lb = __uint_as_float((B << 20) | (B2 << 8));
                rowval = (ps + t + (float)kk2 * lb) / (float)pos;
            }
        }
    }

    if (tid == 0) {
        g_row[n] = rowval;
        __threadfence();
        unsigned old = atomicAdd(&g_count, 1u);
        s_last = (old == N_ - 1u) ? 1u : 0u;
    }
    __syncthreads();

    // ---- last consumer computes the mean ----
    if (s_last) {
        __threadfence();
        float v = (tid < N_) ? g_row[tid] : 0.f;
        for (int o = 16; o > 0; o >>= 1) v += __shfl_down_sync(0xffffffffu, v, o);
        if (lane == 0) s_redf[wid] = v;
        __syncthreads();
        if (tid == 0) {
            float t = s_redf[0] + s_redf[1] + s_redf[2] + s_redf[3];
            out[0] = t / (float)N_;
            g_count = 0u;    // reset for next graph replay
        }
    }
}

extern "C" void kernel_launch(void* const* d_in, const int* in_sizes, int n_in,
                              void* d_out, int out_size)
{
    const float* ploc         = (const float*)d_in[0];
    const float* plabel       = (const float*)d_in[1];
    const float* gloc         = (const float*)d_in[2];
    const int*   glabel       = (const int*)  d_in[3];
    const int*   domain_label = (const int*)  d_in[4];
    const float* dboxes       = (const float*)d_in[5];
    float* out = (float*)d_out;

    k_all<<<9 * N_ + N_, 256, DYN_BYTES>>>(ploc, plabel, gloc, glabel,
                                           domain_label, dboxes, out);
}

// round 11
// speedup vs baseline: 1.0957x; 1.0957x over previous
#include <cuda_runtime.h>
#include <cuda_bf16.h>
#include <cstdint>

#define N_ 128
#define C_ 81
#define A_ 8732
#define A4_ 2183          // A_/4 exactly
#define A4P 3072          // padded uint4 groups (3 * 1024)
#define NB 4096
#define DYN_BYTES ((A4P * 4 + 4 * NB) * 4)   // s_con(12288) + 4 hist replicas = 114688 B

// Scratch (device globals — no allocations allowed)
__device__ unsigned g_con[N_ * A_];
__device__ float    g_partcon[N_ * 16];
__device__ int      g_partpos[N_ * 16];
__device__ float    g_row[N_];
__device__ unsigned g_count;               // self-resetting

// ---------------------------------------------------------------------------
// Kernel A: focal loss per anchor (at its traffic floor — unchanged from R9).
// ---------------------------------------------------------------------------
__global__ __launch_bounds__(256, 8) void kA_focal(const float* __restrict__ plabel,
                                                   const int*   __restrict__ glabel,
                                                   const int*   __restrict__ domain_label)
{
    const int n = blockIdx.y;
    if (domain_label[n] != 0) return;

    int idx = blockIdx.x * 256 + threadIdx.x;
    bool valid = (idx < A4_);
    int ii = valid ? idx : (A4_ - 1);

    const float4* P = (const float4*)(plabel + (size_t)n * C_ * A_) + ii;
    int4 g = ((const int4*)(glabel + (size_t)n * A_))[ii];

    float4 s  = make_float4(0.f, 0.f, 0.f, 0.f);
    float4 xg = make_float4(0.f, 0.f, 0.f, 0.f);
#pragma unroll 3
    for (int c = 0; c < C_; c++) {
        float4 x = __ldcs(P);
        P += A4_;
        if (c == g.x) xg.x = x.x;
        if (c == g.y) xg.y = x.y;
        if (c == g.z) xg.z = x.z;
        if (c == g.w) xg.w = x.w;
        s.x += __expf(x.x); s.y += __expf(x.y);
        s.z += __expf(x.z); s.w += __expf(x.w);
    }

    float lp0 = xg.x - __logf(s.x), lp1 = xg.y - __logf(s.y);
    float lp2 = xg.z - __logf(s.z), lp3 = xg.w - __logf(s.w);
    float o0 = 1.f - __expf(lp0), o1 = 1.f - __expf(lp1);
    float o2 = 1.f - __expf(lp2), o3 = 1.f - __expf(lp3);
    float c0 = -0.25f * o0 * o0 * lp0;
    float c1 = -0.25f * o1 * o1 * lp1;
    float c2 = -0.25f * o2 * o2 * lp2;
    float c3 = -0.25f * o3 * o3 * lp3;

    bool m0 = g.x > 0, m1 = g.y > 0, m2 = g.z > 0, m3 = g.w > 0;

    uint4 cw;
    cw.x = m0 ? 0u : __float_as_uint(c0);
    cw.y = m1 ? 0u : __float_as_uint(c1);
    cw.z = m2 ? 0u : __float_as_uint(c2);
    cw.w = m3 ? 0u : __float_as_uint(c3);
    ((uint4*)g_con)[(size_t)n * A4_ + ii] = cw;

    float contrib = 0.f;
    int pc = 0;
    if (valid) {
        if (m0) { contrib += c0; pc++; }
        if (m1) { contrib += c1; pc++; }
        if (m2) { contrib += c2; pc++; }
        if (m3) { contrib += c3; pc++; }
    }
    for (int o = 16; o > 0; o >>= 1) {
        contrib += __shfl_down_sync(0xffffffffu, contrib, o);
        pc      += __shfl_down_sync(0xffffffffu, pc, o);
    }
    __shared__ float sw[8];
    __shared__ int   swp[8];
    int wid = threadIdx.x >> 5, lane = threadIdx.x & 31;
    if (lane == 0) { sw[wid] = contrib; swp[wid] = pc; }
    __syncthreads();
    if (threadIdx.x == 0) {
        float t = 0.f; int tp = 0;
#pragma unroll
        for (int j = 0; j < 8; j++) { t += sw[j]; tp += swp[j]; }
        g_partcon[n * 16 + blockIdx.x] = t;
        g_partpos[n * 16 + blockIdx.x] = tp;
    }
}

// warp-aggregated smem histogram increment (full-warp, match on bin)
__device__ __forceinline__ void hist_add(unsigned* hist, unsigned bin)
{
    unsigned peers = __match_any_sync(0xffffffffu, bin);
    int leader = __ffs(peers) - 1;
    if ((int)(threadIdx.x & 31) == leader)
        atomicAdd(&hist[bin], (unsigned)__popc(peers));
}

// ---------------------------------------------------------------------------
// Kernel T: per-row tail. Two-level 4096-bin histogram top-k with
// warp-aggregated atomics; s_con padded to 12288 with 0u (provably safe:
// 0-valued ties contribute 0). grid = N_, block = 1024.
// ---------------------------------------------------------------------------
__global__ __launch_bounds__(1024) void kT_tail(const float* __restrict__ ploc,
                                                const float* __restrict__ gloc,
                                                const int*   __restrict__ domain_label,
                                                const float* __restrict__ dboxes,
                                                float* __restrict__ out)
{
    extern __shared__ unsigned dyn[];
    unsigned* s_con  = dyn;              // A4P*4 = 12288 uints (padded)
    unsigned* s_hist = dyn + A4P * 4;    // 4 * 4096

    __shared__ unsigned s_wc[32];
    __shared__ float    s_redf[32];
    __shared__ int      s_B, s_B2;
    __shared__ unsigned s_kk, s_kk2;
    __shared__ float    s_ps;
    __shared__ int      s_pn;
    __shared__ unsigned s_last;

    const int n   = blockIdx.x;
    const int tid = threadIdx.x;
    const int wid = tid >> 5, lane = tid & 31;
    const int dl  = domain_label[n];
    float rowval = 0.f;

    if (dl == 0) {
        if (tid == 0) {
            float ps = 0.f; int pp = 0;
#pragma unroll
            for (int q = 0; q < 9; q++) { ps += g_partcon[n * 16 + q]; pp += g_partpos[n * 16 + q]; }
            s_ps = ps; s_pn = pp;
        }
#pragma unroll
        for (int q = 0; q < 16; q++) s_hist[q * 1024 + tid] = 0u;
        __syncthreads();
        const int pos = s_pn;

        if (pos > 0) {
            const uint4*  gc = (const uint4*)g_con + (size_t)n * A4_;
            const float4* PL = (const float4*)(ploc + (size_t)n * 4 * A_);
            const float4* GL = (const float4*)(gloc + (size_t)n * 4 * A_);
            const float4* DB = (const float4*)dboxes;
            unsigned* h1 = s_hist + ((unsigned)wid & 3u) * NB;

            float acc = 0.f;

            // ===== phase 1: gmem scan -> smem (padded), hist1, sl1 =====
#pragma unroll
            for (int chunk = 0; chunk < 3; chunk++) {
                int grp = chunk * 1024 + tid;
                bool valid = (grp < A4_);
                uint4 x = valid ? __ldcg(gc + grp) : make_uint4(0u, 0u, 0u, 0u);
                ((uint4*)s_con)[grp] = x;
                hist_add(h1, x.x >> 20);
                hist_add(h1, x.y >> 20);
                hist_add(h1, x.z >> 20);
                hist_add(h1, x.w >> 20);

                bool m0 = valid && (x.x == 0u), m1 = valid && (x.y == 0u);
                bool m2 = valid && (x.z == 0u), m3 = valid && (x.w == 0u);
                if (m0 | m1 | m2 | m3) {
                    float4 plx = PL[0 * A4_ + grp], ply = PL[1 * A4_ + grp];
                    float4 plw = PL[2 * A4_ + grp], plh = PL[3 * A4_ + grp];
                    float4 glx = GL[0 * A4_ + grp], gly = GL[1 * A4_ + grp];
                    float4 glw = GL[2 * A4_ + grp], glh = GL[3 * A4_ + grp];
                    float4 dbx = DB[0 * A4_ + grp], dby = DB[1 * A4_ + grp];
                    float4 dbw = DB[2 * A4_ + grp], dbh = DB[3 * A4_ + grp];
#define SL1_LANE(M, PX, PY, PW, PH, GX, GY, GW, GH, DX, DY, DW, DH)           \
                    if (M) {                                                  \
                        float v0 = 10.f * (GX - DX) / DW;                     \
                        float v1 = 10.f * (GY - DY) / DH;                     \
                        float v2 = 5.f * __logf(GW / DW);                     \
                        float v3 = 5.f * __logf(GH / DH);                     \
                        float d0 = PX - v0, d1 = PY - v1;                     \
                        float d2 = PW - v2, d3 = PH - v3;                     \
                        float ad;                                             \
                        ad = fabsf(d0); acc += (ad < 1.f) ? 0.5f*d0*d0 : ad-0.5f; \
                        ad = fabsf(d1); acc += (ad < 1.f) ? 0.5f*d1*d1 : ad-0.5f; \
                        ad = fabsf(d2); acc += (ad < 1.f) ? 0.5f*d2*d2 : ad-0.5f; \
                        ad = fabsf(d3); acc += (ad < 1.f) ? 0.5f*d3*d3 : ad-0.5f; \
                    }
                    SL1_LANE(m0, plx.x, ply.x, plw.x, plh.x, glx.x, gly.x, glw.x, glh.x, dbx.x, dby.x, dbw.x, dbh.x)
                    SL1_LANE(m1, plx.y, ply.y, plw.y, plh.y, glx.y, gly.y, glw.y, glh.y, dbx.y, dby.y, dbw.y, dbh.y)
                    SL1_LANE(m2, plx.z, ply.z, plw.z, plh.z, glx.z, gly.z, glw.z, glh.z, dbx.z, dby.z, dbw.z, dbh.z)
                    SL1_LANE(m3, plx.w, ply.w, plw.w, plh.w, glx.w, gly.w, glw.w, glh.w, dbx.w, dby.w, dbw.w, dbh.w)
#undef SL1_LANE
                }
            }
            __syncthreads();

            const unsigned k = (unsigned)((3 * pos > A_) ? A_ : 3 * pos);

            // ===== scan level-1 (4 bins/thread) -> B, kk =====
            {
                unsigned h[4];
#pragma unroll
                for (int q = 0; q < 4; q++)
                    h[q] = s_hist[4 * tid + q] + s_hist[NB + 4 * tid + q]
                         + s_hist[2 * NB + 4 * tid + q] + s_hist[3 * NB + 4 * tid + q];
                unsigned c = h[0] + h[1] + h[2] + h[3];
#pragma unroll
                for (int o = 1; o < 32; o <<= 1) {
                    unsigned uc = __shfl_down_sync(0xffffffffu, c, o);
                    if (lane + o < 32) c += uc;
                }
                if (lane == 0) s_wc[wid] = c;
                __syncthreads();
                if (tid < 32) {
                    unsigned cc = s_wc[tid];
#pragma unroll
                    for (int o = 1; o < 32; o <<= 1) {
                        unsigned uc = __shfl_down_sync(0xffffffffu, cc, o);
                        if (tid + o < 32) cc += uc;
                    }
                    s_wc[tid] = cc;
                }
                __syncthreads();
                unsigned hi = (wid < 31) ? s_wc[wid + 1] : 0u;
                unsigned suf = c + hi;
#pragma unroll
                for (int q = 0; q < 4; q++) {
                    unsigned gtc = suf - h[q];
                    if (k <= suf && k > gtc) { s_B = 4 * tid + q; s_kk = k - gtc; }
                    suf = gtc;
                }
            }
            __syncthreads();
            const unsigned B  = (unsigned)s_B;
            const unsigned kk = s_kk;

#pragma unroll
            for (int q = 0; q < 16; q++) s_hist[q * 1024 + tid] = 0u;
            __syncthreads();

            // ===== phase 2 (smem, uniform): above-B sum + hist2 =====
#pragma unroll
            for (int chunk = 0; chunk < 3; chunk++) {
                int grp = chunk * 1024 + tid;
                uint4 x = ((const uint4*)s_con)[grp];
#define P2(V)                                                                 \
                {                                                             \
                    unsigned b = (V) >> 20;                                   \
                    if (b > B) acc += __uint_as_float(V);                     \
                    unsigned bin2 = (b == B) ? (((V) >> 8) & 0xFFFu) : 0xFFFFu; \
                    unsigned peers = __match_any_sync(0xffffffffu, bin2);     \
                    if (bin2 != 0xFFFFu && (int)lane == __ffs(peers) - 1)     \
                        atomicAdd(&h1[bin2], (unsigned)__popc(peers));        \
                }
                P2(x.x) P2(x.y) P2(x.z) P2(x.w)
#undef P2
            }
            __syncthreads();

            // ===== scan level-2 -> B2, kk2 =====
            {
                unsigned h[4];
#pragma unroll
                for (int q = 0; q < 4; q++)
                    h[q] = s_hist[4 * tid + q] + s_hist[NB + 4 * tid + q]
                         + s_hist[2 * NB + 4 * tid + q] + s_hist[3 * NB + 4 * tid + q];
                unsigned c = h[0] + h[1] + h[2] + h[3];
#pragma unroll
                for (int o = 1; o < 32; o <<= 1) {
                    unsigned uc = __shfl_down_sync(0xffffffffu, c, o);
                    if (lane + o < 32) c += uc;
                }
                if (lane == 0) s_wc[wid] = c;
                __syncthreads();
                if (tid < 32) {
                    unsigned cc = s_wc[tid];
#pragma unroll
                    for (int o = 1; o < 32; o <<= 1) {
                        unsigned uc = __shfl_down_sync(0xffffffffu, cc, o);
                        if (tid + o < 32) cc += uc;
                    }
                    s_wc[tid] = cc;
                }
                __syncthreads();
                unsigned hi = (wid < 31) ? s_wc[wid + 1] : 0u;
                unsigned suf = c + hi;
#pragma unroll
                for (int q = 0; q < 4; q++) {
                    unsigned gtc = suf - h[q];
                    if (kk <= suf && kk > gtc) { s_B2 = 4 * tid + q; s_kk2 = kk - gtc; }
                    suf = gtc;
                }
            }
            __syncthreads();
            const unsigned B2  = (unsigned)s_B2;
            const unsigned kk2 = s_kk2;

            // ===== phase 3 (smem, uniform): bucket-B above-B2 sum =====
#pragma unroll
            for (int chunk = 0; chunk < 3; chunk++) {
                int grp = chunk * 1024 + tid;
                uint4 x = ((const uint4*)s_con)[grp];
#define P3(V)                                                                 \
                if (((V) >> 20) == B && (((V) >> 8) & 0xFFFu) > B2)           \
                    acc += __uint_as_float(V);
                P3(x.x) P3(x.y) P3(x.z) P3(x.w)
#undef P3
            }

            // ===== single block reduce =====
            for (int o = 16; o > 0; o >>= 1) acc += __shfl_down_sync(0xffffffffu, acc, o);
            if (lane == 0) s_redf[wid] = acc;
            __syncthreads();
            if (tid == 0) {
                float t = 0.f;
#pragma unroll
                for (int q = 0; q < 32; q++) t += s_redf[q];
                float lb = __uint_as_float((B << 20) | (B2 << 8));
                rowval = (s_ps + t + (float)kk2 * lb) / (float)pos;
            }
        }
    }

    if (tid == 0) {
        g_row[n] = rowval;
        __threadfence();
        unsigned old = atomicAdd(&g_count, 1u);
        s_last = (old == N_ - 1u) ? 1u : 0u;
    }
    __syncthreads();

    if (s_last) {
        __threadfence();
        float v = (tid < N_) ? g_row[tid] : 0.f;
        for (int o = 16; o > 0; o >>= 1) v += __shfl_down_sync(0xffffffffu, v, o);
        if (lane == 0) s_redf[wid] = v;
        __syncthreads();
        if (tid == 0) {
            float t = s_redf[0] + s_redf[1] + s_redf[2] + s_redf[3];
            out[0] = t / (float)N_;
            g_count = 0u;   // reset for next graph replay
        }
    }
}

extern "C" void kernel_launch(void* const* d_in, const int* in_sizes, int n_in,
                              void* d_out, int out_size)
{
    const float* ploc         = (const float*)d_in[0];
    const float* plabel       = (const float*)d_in[1];
    const float* gloc         = (const float*)d_in[2];
    const int*   glabel       = (const int*)  d_in[3];
    const int*   domain_label = (const int*)  d_in[4];
    const float* dboxes       = (const float*)d_in[5];
    float* out = (float*)d_out;

    cudaFuncSetAttribute(kT_tail, cudaFuncAttributeMaxDynamicSharedMemorySize, DYN_BYTES);

    dim3 g1(9, N_);
    kA_focal<<<g1, 256>>>(plabel, glabel, domain_label);
    kT_tail<<<N_, 1024, DYN_BYTES>>>(ploc, gloc, domain_label, dboxes, out);
}

// round 12
// speedup vs baseline: 1.1749x; 1.0722x over previous
#include <cuda_runtime.h>
#include <cuda_bf16.h>
#include <cstdint>

#define N_ 128
#define C_ 81
#define A_ 8732
#define A4_ 2183          // A_/4 exactly
#define A4P 3072          // padded uint4 groups (3 * 1024)
#define NB 4096
#define DYN_BYTES ((A4P * 4 + 4 * NB) * 4)   // s_con(12288) + 4 hist replicas = 114688 B

// Scratch (device globals — no allocations allowed)
__device__ unsigned g_con[N_ * A_];
__device__ float    g_partcon[N_ * 16];
__device__ int      g_partpos[N_ * 16];
__device__ float    g_partsl1[N_ * 16];
__device__ float    g_row[N_];
__device__ unsigned g_count;               // self-resetting

// ---------------------------------------------------------------------------
// Kernel B: masked smooth-L1 partial sums. High parallelism (1152 CTAs) hides
// the scattered divergent loads that were killing kT. dl-skip + group-skip.
// grid = (9, N), block = 256.
// ---------------------------------------------------------------------------
__global__ __launch_bounds__(256) void kB_loc(const float* __restrict__ ploc,
                                              const float* __restrict__ gloc,
                                              const int*   __restrict__ glabel,
                                              const int*   __restrict__ domain_label,
                                              const float* __restrict__ dboxes)
{
    const int n = blockIdx.y;
    if (domain_label[n] != 0) return;

    int idx = blockIdx.x * 256 + threadIdx.x;
    bool valid = (idx < A4_);
    int ii = valid ? idx : (A4_ - 1);

    int4 g = ((const int4*)(glabel + (size_t)n * A_))[ii];
    bool m0 = g.x > 0, m1 = g.y > 0, m2 = g.z > 0, m3 = g.w > 0;

    float contrib = 0.f;
    if (valid && (m0 | m1 | m2 | m3)) {
        const float4* PL = (const float4*)(ploc + (size_t)n * 4 * A_);
        const float4* GL = (const float4*)(gloc + (size_t)n * 4 * A_);
        const float4* DB = (const float4*)dboxes;

        float4 plx = PL[0 * A4_ + ii], ply = PL[1 * A4_ + ii];
        float4 plw = PL[2 * A4_ + ii], plh = PL[3 * A4_ + ii];
        float4 glx = GL[0 * A4_ + ii], gly = GL[1 * A4_ + ii];
        float4 glw = GL[2 * A4_ + ii], glh = GL[3 * A4_ + ii];
        float4 dbx = DB[0 * A4_ + ii], dby = DB[1 * A4_ + ii];
        float4 dbw = DB[2 * A4_ + ii], dbh = DB[3 * A4_ + ii];

#define SL1_LANE(M, PX, PY, PW, PH, GX, GY, GW, GH, DX, DY, DW, DH)       \
        if (M) {                                                          \
            float v0 = 10.f * (GX - DX) / DW;                             \
            float v1 = 10.f * (GY - DY) / DH;                             \
            float v2 = 5.f * __logf(GW / DW);                             \
            float v3 = 5.f * __logf(GH / DH);                             \
            float d0 = PX - v0, d1 = PY - v1, d2 = PW - v2, d3 = PH - v3; \
            float ad;                                                     \
            ad = fabsf(d0); contrib += (ad < 1.f) ? 0.5f*d0*d0 : ad-0.5f; \
            ad = fabsf(d1); contrib += (ad < 1.f) ? 0.5f*d1*d1 : ad-0.5f; \
            ad = fabsf(d2); contrib += (ad < 1.f) ? 0.5f*d2*d2 : ad-0.5f; \
            ad = fabsf(d3); contrib += (ad < 1.f) ? 0.5f*d3*d3 : ad-0.5f; \
        }
        SL1_LANE(m0, plx.x, ply.x, plw.x, plh.x, glx.x, gly.x, glw.x, glh.x, dbx.x, dby.x, dbw.x, dbh.x)
        SL1_LANE(m1, plx.y, ply.y, plw.y, plh.y, glx.y, gly.y, glw.y, glh.y, dbx.y, dby.y, dbw.y, dbh.y)
        SL1_LANE(m2, plx.z, ply.z, plw.z, plh.z, glx.z, gly.z, glw.z, glh.z, dbx.z, dby.z, dbw.z, dbh.z)
        SL1_LANE(m3, plx.w, ply.w, plw.w, plh.w, glx.w, gly.w, glw.w, glh.w, dbx.w, dby.w, dbw.w, dbh.w)
#undef SL1_LANE
    }

    for (int o = 16; o > 0; o >>= 1)
        contrib += __shfl_down_sync(0xffffffffu, contrib, o);
    __shared__ float sw[8];
    int wid = threadIdx.x >> 5, lane = threadIdx.x & 31;
    if (lane == 0) sw[wid] = contrib;
    __syncthreads();
    if (threadIdx.x == 0) {
        float t = 0.f;
#pragma unroll
        for (int j = 0; j < 8; j++) t += sw[j];
        g_partsl1[n * 16 + blockIdx.x] = t;
    }
}

// ---------------------------------------------------------------------------
// Kernel A: focal loss per anchor (at its traffic floor — unchanged).
// grid = (9, N), block = 256. Whole block exits when domain_label != 0.
// ---------------------------------------------------------------------------
__global__ __launch_bounds__(256, 8) void kA_focal(const float* __restrict__ plabel,
                                                   const int*   __restrict__ glabel,
                                                   const int*   __restrict__ domain_label)
{
    const int n = blockIdx.y;
    if (domain_label[n] != 0) return;

    int idx = blockIdx.x * 256 + threadIdx.x;
    bool valid = (idx < A4_);
    int ii = valid ? idx : (A4_ - 1);

    const float4* P = (const float4*)(plabel + (size_t)n * C_ * A_) + ii;
    int4 g = ((const int4*)(glabel + (size_t)n * A_))[ii];

    float4 s  = make_float4(0.f, 0.f, 0.f, 0.f);
    float4 xg = make_float4(0.f, 0.f, 0.f, 0.f);
#pragma unroll 3
    for (int c = 0; c < C_; c++) {
        float4 x = __ldcs(P);
        P += A4_;
        if (c == g.x) xg.x = x.x;
        if (c == g.y) xg.y = x.y;
        if (c == g.z) xg.z = x.z;
        if (c == g.w) xg.w = x.w;
        s.x += __expf(x.x); s.y += __expf(x.y);
        s.z += __expf(x.z); s.w += __expf(x.w);
    }

    float lp0 = xg.x - __logf(s.x), lp1 = xg.y - __logf(s.y);
    float lp2 = xg.z - __logf(s.z), lp3 = xg.w - __logf(s.w);
    float o0 = 1.f - __expf(lp0), o1 = 1.f - __expf(lp1);
    float o2 = 1.f - __expf(lp2), o3 = 1.f - __expf(lp3);
    float c0 = -0.25f * o0 * o0 * lp0;
    float c1 = -0.25f * o1 * o1 * lp1;
    float c2 = -0.25f * o2 * o2 * lp2;
    float c3 = -0.25f * o3 * o3 * lp3;

    bool m0 = g.x > 0, m1 = g.y > 0, m2 = g.z > 0, m3 = g.w > 0;

    uint4 cw;
    cw.x = m0 ? 0u : __float_as_uint(c0);
    cw.y = m1 ? 0u : __float_as_uint(c1);
    cw.z = m2 ? 0u : __float_as_uint(c2);
    cw.w = m3 ? 0u : __float_as_uint(c3);
    ((uint4*)g_con)[(size_t)n * A4_ + ii] = cw;

    float contrib = 0.f;
    int pc = 0;
    if (valid) {
        if (m0) { contrib += c0; pc++; }
        if (m1) { contrib += c1; pc++; }
        if (m2) { contrib += c2; pc++; }
        if (m3) { contrib += c3; pc++; }
    }
    for (int o = 16; o > 0; o >>= 1) {
        contrib += __shfl_down_sync(0xffffffffu, contrib, o);
        pc      += __shfl_down_sync(0xffffffffu, pc, o);
    }
    __shared__ float sw[8];
    __shared__ int   swp[8];
    int wid = threadIdx.x >> 5, lane = threadIdx.x & 31;
    if (lane == 0) { sw[wid] = contrib; swp[wid] = pc; }
    __syncthreads();
    if (threadIdx.x == 0) {
        float t = 0.f; int tp = 0;
#pragma unroll
        for (int j = 0; j < 8; j++) { t += sw[j]; tp += swp[j]; }
        g_partcon[n * 16 + blockIdx.x] = t;
        g_partpos[n * 16 + blockIdx.x] = tp;
    }
}

// ---------------------------------------------------------------------------
// Kernel T: select-only per-row tail (two-level 4096-bin histogram top-k).
// No loc pass — that moved to kB. grid = N_, block = 1024.
// ---------------------------------------------------------------------------
__global__ __launch_bounds__(1024) void kT_tail(const int* __restrict__ domain_label,
                                                float* __restrict__ out)
{
    extern __shared__ unsigned dyn[];
    unsigned* s_con  = dyn;              // A4P*4 = 12288 uints (padded with 0u)
    unsigned* s_hist = dyn + A4P * 4;    // 4 * 4096

    __shared__ unsigned s_wc[32];
    __shared__ float    s_redf[32];
    __shared__ int      s_B, s_B2;
    __shared__ unsigned s_kk, s_kk2;
    __shared__ float    s_ps;
    __shared__ int      s_pn;
    __shared__ unsigned s_last;

    const int n   = blockIdx.x;
    const int tid = threadIdx.x;
    const int wid = tid >> 5, lane = tid & 31;
    const int dl  = domain_label[n];
    float rowval = 0.f;

    if (dl == 0) {
        if (tid == 0) {
            float ps = 0.f; int pp = 0;
#pragma unroll
            for (int q = 0; q < 9; q++) {
                ps += g_partcon[n * 16 + q] + g_partsl1[n * 16 + q];
                pp += g_partpos[n * 16 + q];
            }
            s_ps = ps; s_pn = pp;
        }
#pragma unroll
        for (int q = 0; q < 16; q++) s_hist[q * 1024 + tid] = 0u;
        __syncthreads();
        const int pos = s_pn;

        if (pos > 0) {
            const uint4* gc = (const uint4*)g_con + (size_t)n * A4_;
            unsigned* h1 = s_hist + ((unsigned)wid & 3u) * NB;

            float acc = 0.f;

            // ===== phase 1: L2-hot gmem scan -> smem + hist1 =====
#pragma unroll
            for (int chunk = 0; chunk < 3; chunk++) {
                int grp = chunk * 1024 + tid;
                uint4 x = (grp < A4_) ? __ldcg(gc + grp) : make_uint4(0u, 0u, 0u, 0u);
                ((uint4*)s_con)[grp] = x;
                atomicAdd(&h1[x.x >> 20], 1u);
                atomicAdd(&h1[x.y >> 20], 1u);
                atomicAdd(&h1[x.z >> 20], 1u);
                atomicAdd(&h1[x.w >> 20], 1u);
            }
            __syncthreads();

            const unsigned k = (unsigned)((3 * pos > A_) ? A_ : 3 * pos);

            // ===== scan level-1 (4 bins/thread) -> B, kk =====
            {
                unsigned h[4];
#pragma unroll
                for (int q = 0; q < 4; q++)
                    h[q] = s_hist[4 * tid + q] + s_hist[NB + 4 * tid + q]
                         + s_hist[2 * NB + 4 * tid + q] + s_hist[3 * NB + 4 * tid + q];
                unsigned c = h[0] + h[1] + h[2] + h[3];
#pragma unroll
                for (int o = 1; o < 32; o <<= 1) {
                    unsigned uc = __shfl_down_sync(0xffffffffu, c, o);
                    if (lane + o < 32) c += uc;
                }
                if (lane == 0) s_wc[wid] = c;
                __syncthreads();
                if (tid < 32) {
                    unsigned cc = s_wc[tid];
#pragma unroll
                    for (int o = 1; o < 32; o <<= 1) {
                        unsigned uc = __shfl_down_sync(0xffffffffu, cc, o);
                        if (tid + o < 32) cc += uc;
                    }
                    s_wc[tid] = cc;
                }
                __syncthreads();
                unsigned hi = (wid < 31) ? s_wc[wid + 1] : 0u;
                unsigned suf = c + hi;
#pragma unroll
                for (int q = 0; q < 4; q++) {
                    unsigned gtc = suf - h[q];
                    if (k <= suf && k > gtc) { s_B = 4 * tid + q; s_kk = k - gtc; }
                    suf = gtc;
                }
            }
            __syncthreads();
            const unsigned B  = (unsigned)s_B;
            const unsigned kk = s_kk;

#pragma unroll
            for (int q = 0; q < 16; q++) s_hist[q * 1024 + tid] = 0u;
            __syncthreads();

            // ===== phase 2 (smem): above-B sum + hist2 on bucket B =====
#pragma unroll
            for (int chunk = 0; chunk < 3; chunk++) {
                int grp = chunk * 1024 + tid;
                uint4 x = ((const uint4*)s_con)[grp];
#define P2(V)                                                                 \
                {                                                             \
                    unsigned b = (V) >> 20;                                   \
                    if (b > B) acc += __uint_as_float(V);                     \
                    else if (b == B) atomicAdd(&h1[((V) >> 8) & 0xFFFu], 1u); \
                }
                P2(x.x) P2(x.y) P2(x.z) P2(x.w)
#undef P2
            }
            __syncthreads();

            // ===== scan level-2 -> B2, kk2 =====
            {
                unsigned h[4];
#pragma unroll
                for (int q = 0; q < 4; q++)
                    h[q] = s_hist[4 * tid + q] + s_hist[NB + 4 * tid + q]
                         + s_hist[2 * NB + 4 * tid + q] + s_hist[3 * NB + 4 * tid + q];
                unsigned c = h[0] + h[1] + h[2] + h[3];
#pragma unroll
                for (int o = 1; o < 32; o <<= 1) {
                    unsigned uc = __shfl_down_sync(0xffffffffu, c, o);
                    if (lane + o < 32) c += uc;
                }
                if (lane == 0) s_wc[wid] = c;
                __syncthreads();
                if (tid < 32) {
                    unsigned cc = s_wc[tid];
#pragma unroll
                    for (int o = 1; o < 32; o <<= 1) {
                        unsigned uc = __shfl_down_sync(0xffffffffu, cc, o);
                        if (tid + o < 32) cc += uc;
                    }
                    s_wc[tid] = cc;
                }
                __syncthreads();
                unsigned hi = (wid < 31) ? s_wc[wid + 1] : 0u;
                unsigned suf = c + hi;
#pragma unroll
                for (int q = 0; q < 4; q++) {
                    unsigned gtc = suf - h[q];
                    if (kk <= suf && kk > gtc) { s_B2 = 4 * tid + q; s_kk2 = kk - gtc; }
                    suf = gtc;
                }
            }
            __syncthreads();
            const unsigned B2  = (unsigned)s_B2;
            const unsigned kk2 = s_kk2;

            // ===== phase 3 (smem): bucket-B above-B2 sum =====
#pragma unroll
            for (int chunk = 0; chunk < 3; chunk++) {
                int grp = chunk * 1024 + tid;
                uint4 x = ((const uint4*)s_con)[grp];
#define P3(V)                                                                 \
                if (((V) >> 20) == B && (((V) >> 8) & 0xFFFu) > B2)           \
                    acc += __uint_as_float(V);
                P3(x.x) P3(x.y) P3(x.z) P3(x.w)
#undef P3
            }

            // ===== single block reduce =====
            for (int o = 16; o > 0; o >>= 1) acc += __shfl_down_sync(0xffffffffu, acc, o);
            if (lane == 0) s_redf[wid] = acc;
            __syncthreads();
            if (tid == 0) {
                float t = 0.f;
#pragma unroll
                for (int q = 0; q < 32; q++) t += s_redf[q];
                float lb = __uint_as_float((B << 20) | (B2 << 8));
                rowval = (s_ps + t + (float)kk2 * lb) / (float)pos;
            }
        }
    }

    if (tid == 0) {
        g_row[n] = rowval;
        __threadfence();
        unsigned old = atomicAdd(&g_count, 1u);
        s_last = (old == N_ - 1u) ? 1u : 0u;
    }
    __syncthreads();

    if (s_last) {
        __threadfence();
        float v = (tid < N_) ? g_row[tid] : 0.f;
        for (int o = 16; o > 0; o >>= 1) v += __shfl_down_sync(0xffffffffu, v, o);
        if (lane == 0) s_redf[wid] = v;
        __syncthreads();
        if (tid == 0) {
            float t = s_redf[0] + s_redf[1] + s_redf[2] + s_redf[3];
            out[0] = t / (float)N_;
            g_count = 0u;   // reset for next graph replay
        }
    }
}

extern "C" void kernel_launch(void* const* d_in, const int* in_sizes, int n_in,
                              void* d_out, int out_size)
{
    const float* ploc         = (const float*)d_in[0];
    const float* plabel       = (const float*)d_in[1];
    const float* gloc         = (const float*)d_in[2];
    const int*   glabel       = (const int*)  d_in[3];
    const int*   domain_label = (const int*)  d_in[4];
    const float* dboxes       = (const float*)d_in[5];
    float* out = (float*)d_out;

    cudaFuncSetAttribute(kT_tail, cudaFuncAttributeMaxDynamicSharedMemorySize, DYN_BYTES);

    dim3 g1(9, N_);
    kB_loc<<<g1, 256>>>(ploc, gloc, glabel, domain_label, dboxes);
    kA_focal<<<g1, 256>>>(plabel, glabel, domain_label);
    kT_tail<<<N_, 1024, DYN_BYTES>>>(domain_label, out);
}